// round 14
// baseline (speedup 1.0000x reference)
#include <cuda_runtime.h>
#include <cuda_bf16.h>
#include <cstdint>

#define L     768
#define CIN   384
#define CO    32
#define NO    128
#define EPS   1e-5f
#define RPB   8      // rows per prep block

// ---------------- device scratch (no allocations allowed) ----------------
__device__ float          g_base [L * NO];               // bo[d] - (right@Wd)[i,d]
__device__ __nv_bfloat16  g_lh   [L * CO];               // left hi
__device__ __nv_bfloat16  g_ll   [L * CO];               // left lo
__device__ __nv_bfloat16  g_B2h  [(size_t)L * CO * NO];  // per-i B2 hi  [i][c][d]
__device__ __nv_bfloat16  g_B2l  [(size_t)L * CO * NO];  // per-i B2 lo

// ---------------- PTX helpers (family-common, sm_80+) ----------------
__device__ __forceinline__ uint32_t smem_u32(const void* p) {
    uint32_t a;
    asm("{ .reg .u64 t; cvta.to.shared.u64 t, %1; cvt.u32.u64 %0, t; }"
        : "=r"(a) : "l"(p));
    return a;
}
__device__ __forceinline__ void ldsm_x4(uint32_t* r, uint32_t addr) {
    asm volatile("ldmatrix.sync.aligned.m8n8.x4.shared.b16 {%0,%1,%2,%3}, [%4];"
                 : "=r"(r[0]), "=r"(r[1]), "=r"(r[2]), "=r"(r[3]) : "r"(addr));
}
__device__ __forceinline__ void ldsm_x4t(uint32_t* r, uint32_t addr) {
    asm volatile("ldmatrix.sync.aligned.m8n8.x4.trans.shared.b16 {%0,%1,%2,%3}, [%4];"
                 : "=r"(r[0]), "=r"(r[1]), "=r"(r[2]), "=r"(r[3]) : "r"(addr));
}
__device__ __forceinline__ void mma16816(float* d, const uint32_t* a, const uint32_t* b) {
    asm volatile(
        "mma.sync.aligned.m16n8k16.row.col.f32.bf16.bf16.f32 "
        "{%0,%1,%2,%3}, {%4,%5,%6,%7}, {%8,%9}, {%0,%1,%2,%3};"
        : "+f"(d[0]), "+f"(d[1]), "+f"(d[2]), "+f"(d[3])
        : "r"(a[0]), "r"(a[1]), "r"(a[2]), "r"(a[3]), "r"(b[0]), "r"(b[1]));
}
__device__ __forceinline__ void cp16(uint32_t dst, const void* src) {
    asm volatile("cp.async.ca.shared.global [%0], [%1], 16;"
                 :: "r"(dst), "l"(src) : "memory");
}
#define CP_COMMIT() asm volatile("cp.async.commit_group;" ::: "memory")
#define CP_WAIT0()  asm volatile("cp.async.wait_group 0;" ::: "memory")

// ============================================================================
// Kernel A v2: 8 rows/block (96 blocks) -> W re-read traffic cut 8x.
//  warp-per-row LayerNorm (shuffle reduce), register-tiled projections,
//  base + B2 hi/lo produced from smem-resident right.
// ============================================================================
__global__ __launch_bounds__(256)
void prep_kernel(const float* __restrict__ act,  const float* __restrict__ mask,
                 const float* __restrict__ gamma, const float* __restrict__ beta,
                 const float* __restrict__ Wl,   const float* __restrict__ bl,
                 const float* __restrict__ Wr,   const float* __restrict__ br,
                 const float* __restrict__ Wo,   const float* __restrict__ bo)
{
    __shared__ float sx[RPB * CIN];        // 12 KB
    __shared__ float sright[RPB * CO];     // 1 KB

    const int j0   = blockIdx.x * RPB;
    const int t    = threadIdx.x;
    const int lane = t & 31;
    const int wid  = t >> 5;

    // ---- A: load act rows (coalesced) ----
    for (int idx = t; idx < RPB * CIN; idx += 256)
        sx[idx] = act[j0 * CIN + idx];
    __syncthreads();

    // ---- B: LayerNorm, one warp per row, shuffle reductions ----
    {
        const int row = wid;               // 8 warps, 8 rows
        float s = 0.f, s2 = 0.f;
        #pragma unroll
        for (int k = 0; k < CIN / 32; k++) {
            const float v = sx[row * CIN + lane + k * 32];
            s += v; s2 += v * v;
        }
        #pragma unroll
        for (int off = 16; off; off >>= 1) {
            s  += __shfl_xor_sync(0xFFFFFFFFu, s,  off);
            s2 += __shfl_xor_sync(0xFFFFFFFFu, s2, off);
        }
        const float mean = s * (1.f / CIN);
        const float rstd = rsqrtf(s2 * (1.f / CIN) - mean * mean + EPS);
        #pragma unroll
        for (int k = 0; k < CIN / 32; k++) {
            const int c = lane + k * 32;
            sx[row * CIN + c] = (sx[row * CIN + c] - mean) * rstd * gamma[c] + beta[c];
        }
    }
    __syncthreads();

    // ---- C: projections. thread: col = t&63 (l:0-31 / r:32-63), 2 rows ----
    {
        const int col = t & 63;
        const int r0  = (t >> 6) * 2;      // 0,2,4,6
        const bool isL = col < 32;
        const int c = isL ? col : col - 32;
        const float* W = isL ? Wl : Wr;
        const float* x0 = sx + r0 * CIN;
        const float* x1 = x0 + CIN;
        float a0 = 0.f, a1 = 0.f;
        #pragma unroll 8
        for (int ci = 0; ci < CIN; ci++) {
            const float w = W[ci * CO + c];
            a0 = fmaf(x0[ci], w, a0);
            a1 = fmaf(x1[ci], w, a1);
        }
        const float bias = isL ? bl[c] : br[c];
        const float v0 = mask[j0 + r0]     * (a0 + bias);
        const float v1 = mask[j0 + r0 + 1] * (a1 + bias);
        if (isL) {
            const __nv_bfloat16 h0 = __float2bfloat16_rn(v0);
            const __nv_bfloat16 h1 = __float2bfloat16_rn(v1);
            g_lh[(j0 + r0)     * CO + c] = h0;
            g_lh[(j0 + r0 + 1) * CO + c] = h1;
            g_ll[(j0 + r0)     * CO + c] = __float2bfloat16_rn(v0 - __bfloat162float(h0));
            g_ll[(j0 + r0 + 1) * CO + c] = __float2bfloat16_rn(v1 - __bfloat162float(h1));
        } else {
            sright[r0 * CO + c]       = v0;
            sright[(r0 + 1) * CO + c] = v1;
        }
    }
    __syncthreads();

    // ---- D: base[j,d] = bo[d] - sum_c right[j,c]*Wd[c,d] ----
    #pragma unroll
    for (int it = 0; it < (RPB * NO) / 256; it++) {   // 4
        const int idx = t + it * 256;
        const int row = idx >> 7;
        const int d   = idx & 127;
        float bm = 0.f;
        #pragma unroll 8
        for (int c = 0; c < CO; c++)
            bm = fmaf(sright[row * CO + c], Wo[(CO + c) * NO + d], bm);
        g_base[(j0 + row) * NO + d] = bo[d] - bm;
    }

    // ---- E: B2[j][c][d] = right*Wp + Wd, bf16 hi/lo, packed uint32 stores ----
    #pragma unroll 1
    for (int row = 0; row < RPB; row++) {
        const int j = j0 + row;
        #pragma unroll
        for (int it = 0; it < 8; it++) {
            const int c  = (t >> 6) + it * 4;   // 0..31
            const int dp = t & 63;              // d pair index
            const float r = sright[row * CO + c];
            const float2 wp = *(const float2*)&Wo[c * NO + 2 * dp];
            const float2 wd = *(const float2*)&Wo[(CO + c) * NO + 2 * dp];
            const float v0 = fmaf(r, wp.x, wd.x);
            const float v1 = fmaf(r, wp.y, wd.y);
            const __nv_bfloat16 h0 = __float2bfloat16_rn(v0);
            const __nv_bfloat16 h1 = __float2bfloat16_rn(v1);
            const __nv_bfloat16 l0 = __float2bfloat16_rn(v0 - __bfloat162float(h0));
            const __nv_bfloat16 l1 = __float2bfloat16_rn(v1 - __bfloat162float(h1));
            const uint32_t hp = ((uint32_t)__bfloat16_as_ushort(h1) << 16)
                              |  (uint32_t)__bfloat16_as_ushort(h0);
            const uint32_t lp = ((uint32_t)__bfloat16_as_ushort(l1) << 16)
                              |  (uint32_t)__bfloat16_as_ushort(l0);
            const size_t off = ((size_t)j * CO + c) * NO + 2 * dp;
            *(uint32_t*)(g_B2h + off) = hp;
            *(uint32_t*)(g_B2l + off) = lp;
        }
    }
}

// ============================================================================
// Kernel B (R8-verified, 72.0us): block = (i, third), 256 thr, 2 j-tiles of
// 128, block-wide cp.async double-buffered sA, B-fragment reuse, direct
// STG.64 epilogue with streaming hint.
// ============================================================================
#define SA_STRIDE 72
#define SB_STRIDE 136
#define SA_BYTES  (128 * SA_STRIDE * 2)    // 18432
#define SB_OFF    (2 * SA_BYTES)           // 36864
#define SMEM_TOTAL (SB_OFF + 64 * SB_STRIDE * 2)   // 54272

__global__ __launch_bounds__(256, 2)
void big_kernel(float* __restrict__ out)
{
    extern __shared__ char smem[];
    const uint32_t smemBase = smem_u32(smem);

    const int t     = threadIdx.x;
    const int i     = blockIdx.x;
    const int third = blockIdx.y;
    const int lane  = t & 31;
    const int wid   = t >> 5;
    const int mOff  = (wid & 3) * 32;
    const int nOff  = (wid >> 2) * 64;

    // ---- prologue: prefetch tile 0 sA via cp.async ----
    {
        const int jt = third * 256;
        #pragma unroll
        for (int idx = t; idx < 1024; idx += 256) {
            const int j  = idx >> 3;
            const int s  = (idx >> 2) & 1;
            const int ch = idx & 3;
            const void* src = s ? (const void*)(g_ll + (jt + j) * CO + ch * 8)
                                : (const void*)(g_lh + (jt + j) * CO + ch * 8);
            cp16(smemBase + (j * SA_STRIDE + s * 32 + ch * 8) * 2, src);
        }
        CP_COMMIT();
    }

    // ---- stage sB (once per block; B2 L2-resident) ----
    {
        const uint4* srcH = (const uint4*)(g_B2h + (size_t)i * CO * NO);
        const uint4* srcL = (const uint4*)(g_B2l + (size_t)i * CO * NO);
        #pragma unroll
        for (int idx = t; idx < 1024; idx += 256) {
            const int r  = idx >> 4;
            const int ch = idx & 15;
            const uint4 v = (r < 32) ? srcH[r * 16 + ch] : srcL[(r - 32) * 16 + ch];
            *(uint4*)(smem + SB_OFF + (r * SB_STRIDE + ch * 8) * 2) = v;
        }
    }

    // ---- base in registers (constant across tiles) ----
    float2 baseR[8];
    {
        const float* bp = g_base + i * NO + nOff + (lane & 3) * 2;
        #pragma unroll
        for (int nt = 0; nt < 8; nt++)
            baseR[nt] = *(const float2*)(bp + nt * 8);
    }

    const uint32_t bAddr0 = smemBase + SB_OFF +
        ((lane & 15) * SB_STRIDE + nOff + (lane >> 4) * 8) * 2;
    const uint32_t aLaneOff = ((mOff + (lane & 15)) * SA_STRIDE + (lane >> 4) * 8) * 2;

    #pragma unroll 1
    for (int tt = 0; tt < 2; tt++) {
        CP_WAIT0();
        __syncthreads();

        if (tt < 1) {
            const int jt = (third * 2 + tt + 1) * 128;
            const uint32_t dstB = smemBase + SA_BYTES;
            #pragma unroll
            for (int idx = t; idx < 1024; idx += 256) {
                const int j  = idx >> 3;
                const int s  = (idx >> 2) & 1;
                const int ch = idx & 3;
                const void* src = s ? (const void*)(g_ll + (jt + j) * CO + ch * 8)
                                    : (const void*)(g_lh + (jt + j) * CO + ch * 8);
                cp16(dstB + (j * SA_STRIDE + s * 32 + ch * 8) * 2, src);
            }
            CP_COMMIT();
        }

        const uint32_t aAddr0 = smemBase + (tt & 1) * SA_BYTES + aLaneOff;

        float acc[2][8][4];
        #pragma unroll
        for (int nt = 0; nt < 8; nt++) {
            #pragma unroll
            for (int mt = 0; mt < 2; mt++) {
                acc[mt][nt][0] = baseR[nt].x; acc[mt][nt][1] = baseR[nt].y;
                acc[mt][nt][2] = baseR[nt].x; acc[mt][nt][3] = baseR[nt].y;
            }
        }

        uint32_t afP[2][4], afT[2][4], bf[4][4];
        #define LOAD_A(dst, kk) { \
            ldsm_x4(dst[0], aAddr0 + (uint32_t)((kk) * 2)); \
            ldsm_x4(dst[1], aAddr0 + (uint32_t)((16 * SA_STRIDE + (kk)) * 2)); }
        #define LOAD_B(kk) { \
            _Pragma("unroll") \
            for (int q = 0; q < 4; q++) \
                ldsm_x4t(bf[q], bAddr0 + (uint32_t)(((kk) * SB_STRIDE + q * 16) * 2)); }
        #define MMA_ALL(af) { \
            _Pragma("unroll") \
            for (int mt = 0; mt < 2; mt++) \
                _Pragma("unroll") \
                for (int nt = 0; nt < 8; nt++) \
                    mma16816(acc[mt][nt], af[mt], &bf[nt >> 1][(nt & 1) * 2]); }

        LOAD_A(afP, 0);  LOAD_B(0);  MMA_ALL(afP);
        LOAD_A(afT, 32);             MMA_ALL(afT);
                         LOAD_B(32); MMA_ALL(afP);
        LOAD_A(afP, 16); LOAD_B(16); MMA_ALL(afP);
        LOAD_A(afT, 48);             MMA_ALL(afT);
                         LOAD_B(48); MMA_ALL(afP);

        #undef LOAD_A
        #undef LOAD_B
        #undef MMA_ALL

        // ---- epilogue: direct STG.64 (sector-optimal), streaming hint ----
        const int jt = (third * 2 + tt) * 128;
        const int dBase = nOff + (lane & 3) * 2;
        float* outI = out + ((size_t)i * L + jt) * NO;
        #pragma unroll
        for (int mt = 0; mt < 2; mt++) {
            const int r0 = mOff + mt * 16 + (lane >> 2);
            float* p0 = outI + (size_t)r0 * NO;
            float* p1 = p0 + 8 * NO;
            #pragma unroll
            for (int nt = 0; nt < 8; nt++) {
                const int d = dBase + nt * 8;
                __stcs((float2*)(p0 + d), make_float2(acc[mt][nt][0], acc[mt][nt][1]));
                __stcs((float2*)(p1 + d), make_float2(acc[mt][nt][2], acc[mt][nt][3]));
            }
        }
    }
}

// ============================================================================
extern "C" void kernel_launch(void* const* d_in, const int* in_sizes, int n_in,
                              void* d_out, int out_size)
{
    (void)in_sizes; (void)n_in; (void)out_size;
    const float* act   = (const float*)d_in[0];
    const float* mask  = (const float*)d_in[1];
    const float* gamma = (const float*)d_in[2];
    const float* beta  = (const float*)d_in[3];
    const float* Wl    = (const float*)d_in[4];
    const float* bl    = (const float*)d_in[5];
    const float* Wr    = (const float*)d_in[6];
    const float* br    = (const float*)d_in[7];
    const float* Wo    = (const float*)d_in[8];
    const float* bo    = (const float*)d_in[9];
    float* out = (float*)d_out;

    static bool attr_set = false;
    if (!attr_set) {
        cudaFuncSetAttribute(big_kernel,
                             cudaFuncAttributeMaxDynamicSharedMemorySize, SMEM_TOTAL);
        attr_set = true;
    }

    prep_kernel<<<L / RPB, 256>>>(act, mask, gamma, beta, Wl, bl, Wr, br, Wo, bo);

    dim3 grid(L, 3);
    big_kernel<<<grid, 256, SMEM_TOTAL>>>(out);
}

// round 15
// speedup vs baseline: 1.0975x; 1.0975x over previous
#include <cuda_runtime.h>
#include <cuda_bf16.h>
#include <cstdint>

#define L     768
#define CIN   384
#define CO    32
#define NO    128
#define EPS   1e-5f
#define RPB   4      // rows per prep block -> 192 blocks

// ---------------- device scratch (no allocations allowed) ----------------
__device__ float          g_base [L * NO];               // bo[d] - (right@Wd)[i,d]
__device__ __nv_bfloat16  g_lh   [L * CO];               // left hi
__device__ __nv_bfloat16  g_ll   [L * CO];               // left lo
__device__ __nv_bfloat16  g_B2h  [(size_t)L * CO * NO];  // per-i B2 hi  [i][c][d]
__device__ __nv_bfloat16  g_B2l  [(size_t)L * CO * NO];  // per-i B2 lo

// ---------------- PTX helpers (family-common, sm_80+) ----------------
__device__ __forceinline__ uint32_t smem_u32(const void* p) {
    uint32_t a;
    asm("{ .reg .u64 t; cvta.to.shared.u64 t, %1; cvt.u32.u64 %0, t; }"
        : "=r"(a) : "l"(p));
    return a;
}
__device__ __forceinline__ void ldsm_x4(uint32_t* r, uint32_t addr) {
    asm volatile("ldmatrix.sync.aligned.m8n8.x4.shared.b16 {%0,%1,%2,%3}, [%4];"
                 : "=r"(r[0]), "=r"(r[1]), "=r"(r[2]), "=r"(r[3]) : "r"(addr));
}
__device__ __forceinline__ void ldsm_x4t(uint32_t* r, uint32_t addr) {
    asm volatile("ldmatrix.sync.aligned.m8n8.x4.trans.shared.b16 {%0,%1,%2,%3}, [%4];"
                 : "=r"(r[0]), "=r"(r[1]), "=r"(r[2]), "=r"(r[3]) : "r"(addr));
}
__device__ __forceinline__ void mma16816(float* d, const uint32_t* a, const uint32_t* b) {
    asm volatile(
        "mma.sync.aligned.m16n8k16.row.col.f32.bf16.bf16.f32 "
        "{%0,%1,%2,%3}, {%4,%5,%6,%7}, {%8,%9}, {%0,%1,%2,%3};"
        : "+f"(d[0]), "+f"(d[1]), "+f"(d[2]), "+f"(d[3])
        : "r"(a[0]), "r"(a[1]), "r"(a[2]), "r"(a[3]), "r"(b[0]), "r"(b[1]));
}
__device__ __forceinline__ void cp16(uint32_t dst, const void* src) {
    asm volatile("cp.async.ca.shared.global [%0], [%1], 16;"
                 :: "r"(dst), "l"(src) : "memory");
}
#define CP_COMMIT() asm volatile("cp.async.commit_group;" ::: "memory")
#define CP_WAIT0()  asm volatile("cp.async.wait_group 0;" ::: "memory")

// ============================================================================
// Kernel A v3: 4 rows/block (192 blocks).
//  - warp-per-row LayerNorm (shuffle reduce, warps 0-3)
//  - projection: thread = (lr, quarter, c); 96-long dots, W value loaded once
//    and FMA'd into 4 row-accumulators (ILP 4, W traffic /4)
//  - base + B2 hi/lo from smem-resident right
// ============================================================================
__global__ __launch_bounds__(256)
void prep_kernel(const float* __restrict__ act,  const float* __restrict__ mask,
                 const float* __restrict__ gamma, const float* __restrict__ beta,
                 const float* __restrict__ Wl,   const float* __restrict__ bl,
                 const float* __restrict__ Wr,   const float* __restrict__ br,
                 const float* __restrict__ Wo,   const float* __restrict__ bo)
{
    __shared__ float sx[RPB * CIN];         // 6 KB
    __shared__ float sdotA[RPB * 256];      // 4 KB (partials per row)
    __shared__ float sright[RPB * CO];      // 512 B

    const int j0   = blockIdx.x * RPB;
    const int t    = threadIdx.x;
    const int lane = t & 31;
    const int wid  = t >> 5;

    // ---- A: load act rows (coalesced) ----
    for (int idx = t; idx < RPB * CIN; idx += 256)
        sx[idx] = act[j0 * CIN + idx];
    __syncthreads();

    // ---- B: LayerNorm, warps 0-3, one per row, shuffle reductions ----
    if (wid < RPB) {
        const int row = wid;
        float s = 0.f, s2 = 0.f;
        #pragma unroll
        for (int k = 0; k < CIN / 32; k++) {
            const float v = sx[row * CIN + lane + k * 32];
            s += v; s2 += v * v;
        }
        #pragma unroll
        for (int off = 16; off; off >>= 1) {
            s  += __shfl_xor_sync(0xFFFFFFFFu, s,  off);
            s2 += __shfl_xor_sync(0xFFFFFFFFu, s2, off);
        }
        const float mean = s * (1.f / CIN);
        const float rstd = rsqrtf(s2 * (1.f / CIN) - mean * mean + EPS);
        #pragma unroll
        for (int k = 0; k < CIN / 32; k++) {
            const int c = lane + k * 32;
            sx[row * CIN + c] = (sx[row * CIN + c] - mean) * rstd * gamma[c] + beta[c];
        }
    }
    __syncthreads();

    // ---- C: projections. thread = (lr = t>>7, q = (t>>5)&3, c = t&31) ----
    //      W loaded once per ci, FMA into 4 row-accumulators (ILP 4).
    {
        const int lr = t >> 7;
        const int q  = (t >> 5) & 3;
        const int c  = t & 31;
        const float* W = lr ? Wr : Wl;
        const int ci0  = q * (CIN / 4);
        float a0 = 0.f, a1 = 0.f, a2 = 0.f, a3 = 0.f;
        #pragma unroll 4
        for (int ci = ci0; ci < ci0 + CIN / 4; ci++) {
            const float w = W[ci * CO + c];
            a0 = fmaf(sx[ci], w, a0);
            a1 = fmaf(sx[CIN + ci], w, a1);
            a2 = fmaf(sx[2 * CIN + ci], w, a2);
            a3 = fmaf(sx[3 * CIN + ci], w, a3);
        }
        sdotA[0 * 256 + t] = a0;
        sdotA[1 * 256 + t] = a1;
        sdotA[2 * 256 + t] = a2;
        sdotA[3 * 256 + t] = a3;
    }
    __syncthreads();
    if (((t >> 5) & 3) == 0) {   // q == 0 threads combine (64: lr x c)
        const int lr = t >> 7;
        const int c  = t & 31;
        const float bias = lr ? br[c] : bl[c];
        #pragma unroll
        for (int row = 0; row < RPB; row++) {
            const float* p = sdotA + row * 256 + t;
            const float val = mask[j0 + row] * (p[0] + p[32] + p[64] + p[96] + bias);
            if (lr == 0) {
                const __nv_bfloat16 h = __float2bfloat16_rn(val);
                g_lh[(j0 + row) * CO + c] = h;
                g_ll[(j0 + row) * CO + c] =
                    __float2bfloat16_rn(val - __bfloat162float(h));
            } else {
                sright[row * CO + c] = val;
            }
        }
    }
    __syncthreads();

    // ---- D: base[j,d] = bo[d] - sum_c right[j,c]*Wd[c,d] ----
    #pragma unroll
    for (int it = 0; it < (RPB * NO) / 256; it++) {   // 2
        const int idx = t + it * 256;
        const int row = idx >> 7;
        const int d   = idx & 127;
        float bm = 0.f;
        #pragma unroll 8
        for (int c = 0; c < CO; c++)
            bm = fmaf(sright[row * CO + c], Wo[(CO + c) * NO + d], bm);
        g_base[(j0 + row) * NO + d] = bo[d] - bm;
    }

    // ---- E: B2[j][c][d] = right*Wp + Wd, bf16 hi/lo, packed uint32 stores ----
    #pragma unroll 1
    for (int row = 0; row < RPB; row++) {
        const int j = j0 + row;
        #pragma unroll
        for (int it = 0; it < 8; it++) {
            const int c  = (t >> 6) + it * 4;   // 0..31
            const int dp = t & 63;              // d pair index
            const float r = sright[row * CO + c];
            const float2 wp = *(const float2*)&Wo[c * NO + 2 * dp];
            const float2 wd = *(const float2*)&Wo[(CO + c) * NO + 2 * dp];
            const float v0 = fmaf(r, wp.x, wd.x);
            const float v1 = fmaf(r, wp.y, wd.y);
            const __nv_bfloat16 h0 = __float2bfloat16_rn(v0);
            const __nv_bfloat16 h1 = __float2bfloat16_rn(v1);
            const __nv_bfloat16 l0 = __float2bfloat16_rn(v0 - __bfloat162float(h0));
            const __nv_bfloat16 l1 = __float2bfloat16_rn(v1 - __bfloat162float(h1));
            const uint32_t hp = ((uint32_t)__bfloat16_as_ushort(h1) << 16)
                              |  (uint32_t)__bfloat16_as_ushort(h0);
            const uint32_t lp = ((uint32_t)__bfloat16_as_ushort(l1) << 16)
                              |  (uint32_t)__bfloat16_as_ushort(l0);
            const size_t off = ((size_t)j * CO + c) * NO + 2 * dp;
            *(uint32_t*)(g_B2h + off) = hp;
            *(uint32_t*)(g_B2l + off) = lp;
        }
    }
}

// ============================================================================
// Kernel B (R8-verified, ~72.0-72.8us across 3 reruns): unchanged.
// ============================================================================
#define SA_STRIDE 72
#define SB_STRIDE 136
#define SA_BYTES  (128 * SA_STRIDE * 2)    // 18432
#define SB_OFF    (2 * SA_BYTES)           // 36864
#define SMEM_TOTAL (SB_OFF + 64 * SB_STRIDE * 2)   // 54272

__global__ __launch_bounds__(256, 2)
void big_kernel(float* __restrict__ out)
{
    extern __shared__ char smem[];
    const uint32_t smemBase = smem_u32(smem);

    const int t     = threadIdx.x;
    const int i     = blockIdx.x;
    const int third = blockIdx.y;
    const int lane  = t & 31;
    const int wid   = t >> 5;
    const int mOff  = (wid & 3) * 32;
    const int nOff  = (wid >> 2) * 64;

    // ---- prologue: prefetch tile 0 sA via cp.async ----
    {
        const int jt = third * 256;
        #pragma unroll
        for (int idx = t; idx < 1024; idx += 256) {
            const int j  = idx >> 3;
            const int s  = (idx >> 2) & 1;
            const int ch = idx & 3;
            const void* src = s ? (const void*)(g_ll + (jt + j) * CO + ch * 8)
                                : (const void*)(g_lh + (jt + j) * CO + ch * 8);
            cp16(smemBase + (j * SA_STRIDE + s * 32 + ch * 8) * 2, src);
        }
        CP_COMMIT();
    }

    // ---- stage sB (once per block; B2 L2-resident) ----
    {
        const uint4* srcH = (const uint4*)(g_B2h + (size_t)i * CO * NO);
        const uint4* srcL = (const uint4*)(g_B2l + (size_t)i * CO * NO);
        #pragma unroll
        for (int idx = t; idx < 1024; idx += 256) {
            const int r  = idx >> 4;
            const int ch = idx & 15;
            const uint4 v = (r < 32) ? srcH[r * 16 + ch] : srcL[(r - 32) * 16 + ch];
            *(uint4*)(smem + SB_OFF + (r * SB_STRIDE + ch * 8) * 2) = v;
        }
    }

    // ---- base in registers (constant across tiles) ----
    float2 baseR[8];
    {
        const float* bp = g_base + i * NO + nOff + (lane & 3) * 2;
        #pragma unroll
        for (int nt = 0; nt < 8; nt++)
            baseR[nt] = *(const float2*)(bp + nt * 8);
    }

    const uint32_t bAddr0 = smemBase + SB_OFF +
        ((lane & 15) * SB_STRIDE + nOff + (lane >> 4) * 8) * 2;
    const uint32_t aLaneOff = ((mOff + (lane & 15)) * SA_STRIDE + (lane >> 4) * 8) * 2;

    #pragma unroll 1
    for (int tt = 0; tt < 2; tt++) {
        CP_WAIT0();
        __syncthreads();

        if (tt < 1) {
            const int jt = (third * 2 + tt + 1) * 128;
            const uint32_t dstB = smemBase + SA_BYTES;
            #pragma unroll
            for (int idx = t; idx < 1024; idx += 256) {
                const int j  = idx >> 3;
                const int s  = (idx >> 2) & 1;
                const int ch = idx & 3;
                const void* src = s ? (const void*)(g_ll + (jt + j) * CO + ch * 8)
                                    : (const void*)(g_lh + (jt + j) * CO + ch * 8);
                cp16(dstB + (j * SA_STRIDE + s * 32 + ch * 8) * 2, src);
            }
            CP_COMMIT();
        }

        const uint32_t aAddr0 = smemBase + (tt & 1) * SA_BYTES + aLaneOff;

        float acc[2][8][4];
        #pragma unroll
        for (int nt = 0; nt < 8; nt++) {
            #pragma unroll
            for (int mt = 0; mt < 2; mt++) {
                acc[mt][nt][0] = baseR[nt].x; acc[mt][nt][1] = baseR[nt].y;
                acc[mt][nt][2] = baseR[nt].x; acc[mt][nt][3] = baseR[nt].y;
            }
        }

        uint32_t afP[2][4], afT[2][4], bf[4][4];
        #define LOAD_A(dst, kk) { \
            ldsm_x4(dst[0], aAddr0 + (uint32_t)((kk) * 2)); \
            ldsm_x4(dst[1], aAddr0 + (uint32_t)((16 * SA_STRIDE + (kk)) * 2)); }
        #define LOAD_B(kk) { \
            _Pragma("unroll") \
            for (int q = 0; q < 4; q++) \
                ldsm_x4t(bf[q], bAddr0 + (uint32_t)(((kk) * SB_STRIDE + q * 16) * 2)); }
        #define MMA_ALL(af) { \
            _Pragma("unroll") \
            for (int mt = 0; mt < 2; mt++) \
                _Pragma("unroll") \
                for (int nt = 0; nt < 8; nt++) \
                    mma16816(acc[mt][nt], af[mt], &bf[nt >> 1][(nt & 1) * 2]); }

        LOAD_A(afP, 0);  LOAD_B(0);  MMA_ALL(afP);
        LOAD_A(afT, 32);             MMA_ALL(afT);
                         LOAD_B(32); MMA_ALL(afP);
        LOAD_A(afP, 16); LOAD_B(16); MMA_ALL(afP);
        LOAD_A(afT, 48);             MMA_ALL(afT);
                         LOAD_B(48); MMA_ALL(afP);

        #undef LOAD_A
        #undef LOAD_B
        #undef MMA_ALL

        // ---- epilogue: direct STG.64 (sector-optimal), streaming hint ----
        const int jt = (third * 2 + tt) * 128;
        const int dBase = nOff + (lane & 3) * 2;
        float* outI = out + ((size_t)i * L + jt) * NO;
        #pragma unroll
        for (int mt = 0; mt < 2; mt++) {
            const int r0 = mOff + mt * 16 + (lane >> 2);
            float* p0 = outI + (size_t)r0 * NO;
            float* p1 = p0 + 8 * NO;
            #pragma unroll
            for (int nt = 0; nt < 8; nt++) {
                const int d = dBase + nt * 8;
                __stcs((float2*)(p0 + d), make_float2(acc[mt][nt][0], acc[mt][nt][1]));
                __stcs((float2*)(p1 + d), make_float2(acc[mt][nt][2], acc[mt][nt][3]));
            }
        }
    }
}

// ============================================================================
extern "C" void kernel_launch(void* const* d_in, const int* in_sizes, int n_in,
                              void* d_out, int out_size)
{
    (void)in_sizes; (void)n_in; (void)out_size;
    const float* act   = (const float*)d_in[0];
    const float* mask  = (const float*)d_in[1];
    const float* gamma = (const float*)d_in[2];
    const float* beta  = (const float*)d_in[3];
    const float* Wl    = (const float*)d_in[4];
    const float* bl    = (const float*)d_in[5];
    const float* Wr    = (const float*)d_in[6];
    const float* br    = (const float*)d_in[7];
    const float* Wo    = (const float*)d_in[8];
    const float* bo    = (const float*)d_in[9];
    float* out = (float*)d_out;

    static bool attr_set = false;
    if (!attr_set) {
        cudaFuncSetAttribute(big_kernel,
                             cudaFuncAttributeMaxDynamicSharedMemorySize, SMEM_TOTAL);
        attr_set = true;
    }

    prep_kernel<<<L / RPB, 256>>>(act, mask, gamma, beta, Wl, bl, Wr, br, Wo, bo);

    dim3 grid(L, 3);
    big_kernel<<<grid, 256, SMEM_TOTAL>>>(out);
}